// round 2
// baseline (speedup 1.0000x reference)
#include <cuda_runtime.h>
#include <math.h>

#define NTOK 4096
#define CDIM 1024
#define HDIM 4096
#define NEXP 8
#define NSLOT (NTOK * 2)

// ---- scratch (static device allocations only) ----
__device__ int   g_counts[NEXP];
__device__ int   g_offsets[NEXP + 1];
__device__ int   g_cursor[NEXP];
__device__ int   g_rtok[NSLOT];
__device__ float g_rw[NSLOT];
__device__ int   g_e1[NTOK], g_e2[NTOK];
__device__ float g_w1[NTOK], g_w2[NTOK];
__device__ float g_h[(size_t)NSLOT * HDIM];   // 128 MiB expert-hidden scratch

__device__ __forceinline__ float gelu_exact(float v) {
    return 0.5f * v * (1.0f + erff(v * 0.70710678118654752f));
}

__global__ void k_init() {
    int t = threadIdx.x;
    if (t < NEXP) g_counts[t] = 0;
}

// One warp per token: gate logits, top-2, renormalized softmax weights.
__global__ void k_gate(const float* __restrict__ x, const float* __restrict__ Wg,
                       const float* __restrict__ bg) {
    int warp = (blockIdx.x * blockDim.x + threadIdx.x) >> 5;
    int lane = threadIdx.x & 31;
    if (warp >= NTOK) return;
    const float* xr = x + (size_t)warp * CDIM;
    float acc[NEXP];
#pragma unroll
    for (int e = 0; e < NEXP; e++) acc[e] = 0.f;
    for (int k = lane; k < CDIM; k += 32) {
        float xv = xr[k];
        const float* wr = Wg + k * NEXP;
#pragma unroll
        for (int e = 0; e < NEXP; e++) acc[e] = fmaf(xv, wr[e], acc[e]);
    }
#pragma unroll
    for (int off = 16; off; off >>= 1)
#pragma unroll
        for (int e = 0; e < NEXP; e++)
            acc[e] += __shfl_xor_sync(0xffffffffu, acc[e], off);
    if (lane == 0) {
#pragma unroll
        for (int e = 0; e < NEXP; e++) acc[e] += bg[e];
        int b1i = 0; float b1v = acc[0];
#pragma unroll
        for (int e = 1; e < NEXP; e++) if (acc[e] > b1v) { b1v = acc[e]; b1i = e; }
        int b2i = -1; float b2v = -3.0e38f;
#pragma unroll
        for (int e = 0; e < NEXP; e++)
            if (e != b1i && acc[e] > b2v) { b2v = acc[e]; b2i = e; }
        // softmax over top-2 == renormalized full softmax restricted to top-2
        float p2 = expf(b2v - b1v);
        float inv = 1.f / (1.f + p2);
        g_e1[warp] = b1i; g_e2[warp] = b2i;
        g_w1[warp] = inv; g_w2[warp] = p2 * inv;
        atomicAdd(&g_counts[b1i], 1);
        atomicAdd(&g_counts[b2i], 1);
    }
}

__global__ void k_prefix() {
    if (threadIdx.x == 0 && blockIdx.x == 0) {
        int off = 0;
        for (int e = 0; e < NEXP; e++) {
            g_offsets[e] = off;
            g_cursor[e]  = off;
            off += g_counts[e];
        }
        g_offsets[NEXP] = off;
    }
}

__global__ void k_scatter() {
    int t = blockIdx.x * blockDim.x + threadIdx.x;
    if (t >= NTOK) return;
    int s1 = atomicAdd(&g_cursor[g_e1[t]], 1);
    g_rtok[s1] = t; g_rw[s1] = g_w1[t];
    int s2 = atomicAdd(&g_cursor[g_e2[t]], 1);
    g_rtok[s2] = t; g_rw[s2] = g_w2[t];
}

__global__ void k_zero(float* __restrict__ out, int n4) {
    int i = blockIdx.x * blockDim.x + threadIdx.x;
    if (i < n4) ((float4*)out)[i] = make_float4(0.f, 0.f, 0.f, 0.f);
}

// GEMM1: h[slot, :H] = gelu(x[token(slot)] @ W1[e] + b1[e])
// 128x128x8 tile, 256 threads, 8x8 per-thread microtile.
__global__ __launch_bounds__(256, 2)
void k_gemm1(const float* __restrict__ x, const float* __restrict__ W1,
             const float* __restrict__ b1) {
    const int e  = blockIdx.z;
    const int off = g_offsets[e];
    const int ne  = g_offsets[e + 1] - off;
    const int m0  = blockIdx.y * 128;
    if (m0 >= ne) return;
    const int n0  = blockIdx.x * 128;
    const float* __restrict__ Bp   = W1 + (size_t)e * CDIM * HDIM;  // [C][H]
    const float* __restrict__ bias = b1 + e * HDIM;

    __shared__ float As[8][128];
    __shared__ float Bs[8][128];

    const int tid = threadIdx.x;
    const int a_m = tid >> 1;
    const int a_k = (tid & 1) << 2;
    const int arow = m0 + a_m;
    const float* a_src = (arow < ne) ? (x + (size_t)g_rtok[off + arow] * CDIM) : nullptr;
    const int b_k = tid >> 5;
    const int b_n = (tid & 31) << 2;
    const int ty = tid >> 4;
    const int tx = tid & 15;

    float acc[8][8];
#pragma unroll
    for (int i = 0; i < 8; i++)
#pragma unroll
        for (int j = 0; j < 8; j++) acc[i][j] = 0.f;

    for (int kt = 0; kt < CDIM; kt += 8) {
        float4 av = make_float4(0.f, 0.f, 0.f, 0.f);
        if (a_src) av = *(const float4*)(a_src + kt + a_k);
        As[a_k + 0][a_m] = av.x;
        As[a_k + 1][a_m] = av.y;
        As[a_k + 2][a_m] = av.z;
        As[a_k + 3][a_m] = av.w;
        *(float4*)&Bs[b_k][b_n] =
            *(const float4*)(Bp + (size_t)(kt + b_k) * HDIM + n0 + b_n);
        __syncthreads();
#pragma unroll
        for (int k = 0; k < 8; k++) {
            float a[8], b[8];
#pragma unroll
            for (int i = 0; i < 8; i++) a[i] = As[k][ty * 8 + i];
#pragma unroll
            for (int j = 0; j < 8; j++) b[j] = Bs[k][tx * 8 + j];
#pragma unroll
            for (int i = 0; i < 8; i++)
#pragma unroll
                for (int j = 0; j < 8; j++)
                    acc[i][j] = fmaf(a[i], b[j], acc[i][j]);
        }
        __syncthreads();
    }

#pragma unroll
    for (int i = 0; i < 8; i++) {
        int r = m0 + ty * 8 + i;
        if (r < ne) {
            float* hrow = g_h + (size_t)(off + r) * HDIM + n0;
#pragma unroll
            for (int j = 0; j < 8; j++) {
                int n = tx * 8 + j;
                hrow[n] = gelu_exact(acc[i][j] + bias[n0 + n]);
            }
        }
    }
}

// GEMM2: out[token] += w(slot) * (h[slot] @ W2[e] + b2[e])
__global__ __launch_bounds__(256, 2)
void k_gemm2(const float* __restrict__ W2, const float* __restrict__ b2,
             float* __restrict__ out) {
    const int e  = blockIdx.z;
    const int off = g_offsets[e];
    const int ne  = g_offsets[e + 1] - off;
    const int m0  = blockIdx.y * 128;
    if (m0 >= ne) return;
    const int n0  = blockIdx.x * 128;
    const float* __restrict__ Bp   = W2 + (size_t)e * HDIM * CDIM;  // [H][C]
    const float* __restrict__ bias = b2 + e * CDIM;

    __shared__ float As[8][128];
    __shared__ float Bs[8][128];

    const int tid = threadIdx.x;
    const int a_m = tid >> 1;
    const int a_k = (tid & 1) << 2;
    const int arow = m0 + a_m;
    const float* a_src = (arow < ne) ? (g_h + (size_t)(off + arow) * HDIM) : nullptr;
    const int b_k = tid >> 5;
    const int b_n = (tid & 31) << 2;
    const int ty = tid >> 4;
    const int tx = tid & 15;

    float acc[8][8];
#pragma unroll
    for (int i = 0; i < 8; i++)
#pragma unroll
        for (int j = 0; j < 8; j++) acc[i][j] = 0.f;

    for (int kt = 0; kt < HDIM; kt += 8) {
        float4 av = make_float4(0.f, 0.f, 0.f, 0.f);
        if (a_src) av = *(const float4*)(a_src + kt + a_k);
        As[a_k + 0][a_m] = av.x;
        As[a_k + 1][a_m] = av.y;
        As[a_k + 2][a_m] = av.z;
        As[a_k + 3][a_m] = av.w;
        *(float4*)&Bs[b_k][b_n] =
            *(const float4*)(Bp + (size_t)(kt + b_k) * CDIM + n0 + b_n);
        __syncthreads();
#pragma unroll
        for (int k = 0; k < 8; k++) {
            float a[8], b[8];
#pragma unroll
            for (int i = 0; i < 8; i++) a[i] = As[k][ty * 8 + i];
#pragma unroll
            for (int j = 0; j < 8; j++) b[j] = Bs[k][tx * 8 + j];
#pragma unroll
            for (int i = 0; i < 8; i++)
#pragma unroll
                for (int j = 0; j < 8; j++)
                    acc[i][j] = fmaf(a[i], b[j], acc[i][j]);
        }
        __syncthreads();
    }

#pragma unroll
    for (int i = 0; i < 8; i++) {
        int r = m0 + ty * 8 + i;
        if (r < ne) {
            int tok = g_rtok[off + r];
            float w = g_rw[off + r];
            float* orow = out + (size_t)tok * CDIM + n0;
#pragma unroll
            for (int j = 0; j < 8; j++) {
                int n = tx * 8 + j;
                atomicAdd(&orow[n], w * (acc[i][j] + bias[n0 + n]));
            }
        }
    }
}

extern "C" void kernel_launch(void* const* d_in, const int* in_sizes, int n_in,
                              void* d_out, int out_size) {
    const float* x  = (const float*)d_in[0];
    const float* Wg = (const float*)d_in[1];
    const float* bg = (const float*)d_in[2];
    const float* W1 = (const float*)d_in[3];
    const float* b1 = (const float*)d_in[4];
    const float* W2 = (const float*)d_in[5];
    const float* b2 = (const float*)d_in[6];
    float* out = (float*)d_out;

    k_init<<<1, 32>>>();
    k_gate<<<(NTOK * 32 + 255) / 256, 256>>>(x, Wg, bg);
    k_prefix<<<1, 1>>>();
    k_scatter<<<(NTOK + 255) / 256, 256>>>();
    k_zero<<<(NTOK * CDIM / 4 + 255) / 256, 256>>>(out, NTOK * CDIM / 4);

    dim3 g1(HDIM / 128, 32, NEXP);   // worst-case M tiles; empty tiles exit early
    k_gemm1<<<g1, 256>>>(x, W1, b1);
    dim3 g2(CDIM / 128, 32, NEXP);
    k_gemm2<<<g2, 256>>>(W2, b2, out);
}

// round 5
// speedup vs baseline: 2.1071x; 2.1071x over previous
#include <cuda_runtime.h>
#include <math.h>
#include <stdint.h>

#define NTOK 4096
#define CDIM 1024
#define HDIM 4096
#define NEXP 8
#define NSLOT (NTOK * 2)

// ---------------- static device scratch ----------------
__device__ int g_counts[NEXP];
__device__ int g_offsets[NEXP + 1];
__device__ int g_cursor[NEXP];
__device__ __align__(16) int g_rtok[NSLOT];
__device__ int g_e1[NTOK], g_e2[NTOK];
__device__ int g_s1[NTOK], g_s2[NTOK];
__device__ float g_w1[NTOK], g_w2[NTOK];
__device__ __align__(256) float g_h[(size_t)NSLOT * HDIM];   // 128 MiB
__device__ __align__(256) float g_y[(size_t)NSLOT * CDIM];   // 32 MiB

// ---------------- helpers ----------------
__device__ __forceinline__ uint32_t smem_u32(const void* p) {
    uint32_t a;
    asm("{ .reg .u64 t; cvta.to.shared.u64 t, %1; cvt.u32.u64 %0, t; }" : "=r"(a) : "l"(p));
    return a;
}
__device__ __forceinline__ uint32_t f2tf(float f) {
    uint32_t r; asm("cvt.rna.tf32.f32 %0, %1;" : "=r"(r) : "f"(f)); return r;
}
#define SWZ(o) ((o) ^ ((((uint32_t)(o)) >> 3) & 0x70u))

__device__ __forceinline__ void sts4(uint32_t a, uint32_t x, uint32_t y, uint32_t z, uint32_t w) {
    asm volatile("st.shared.v4.b32 [%0], {%1,%2,%3,%4};" :: "r"(a), "r"(x), "r"(y), "r"(z), "r"(w) : "memory");
}
__device__ __forceinline__ uint32_t lds32(uint32_t a) {
    uint32_t v; asm volatile("ld.shared.b32 %0, [%1];" : "=r"(v) : "r"(a)); return v;
}
__device__ __forceinline__ void mma_tf32(float* c, const uint32_t a[4], uint32_t b0, uint32_t b1) {
    asm volatile(
        "mma.sync.aligned.m16n8k8.row.col.f32.tf32.tf32.f32 "
        "{%0,%1,%2,%3}, {%4,%5,%6,%7}, {%8,%9}, {%0,%1,%2,%3};"
        : "+f"(c[0]), "+f"(c[1]), "+f"(c[2]), "+f"(c[3])
        : "r"(a[0]), "r"(a[1]), "r"(a[2]), "r"(a[3]), "r"(b0), "r"(b1));
}
__device__ __forceinline__ float gelu_exact(float v) {
    return 0.5f * v * (1.0f + erff(v * 0.70710678118654752f));
}

// ---------------- routing kernels ----------------
__global__ void k_init() {
    int t = threadIdx.x;
    if (t < NEXP) g_counts[t] = 0;
}

__global__ void k_gate(const float* __restrict__ x, const float* __restrict__ Wg,
                       const float* __restrict__ bg) {
    int warp = (blockIdx.x * blockDim.x + threadIdx.x) >> 5;
    int lane = threadIdx.x & 31;
    if (warp >= NTOK) return;
    const float* xr = x + (size_t)warp * CDIM;
    float acc[NEXP];
#pragma unroll
    for (int e = 0; e < NEXP; e++) acc[e] = 0.f;
    for (int k = lane; k < CDIM; k += 32) {
        float xv = xr[k];
        const float* wr = Wg + k * NEXP;
#pragma unroll
        for (int e = 0; e < NEXP; e++) acc[e] = fmaf(xv, wr[e], acc[e]);
    }
#pragma unroll
    for (int off = 16; off; off >>= 1)
#pragma unroll
        for (int e = 0; e < NEXP; e++)
            acc[e] += __shfl_xor_sync(0xffffffffu, acc[e], off);
    if (lane == 0) {
#pragma unroll
        for (int e = 0; e < NEXP; e++) acc[e] += bg[e];
        int b1i = 0; float b1v = acc[0];
#pragma unroll
        for (int e = 1; e < NEXP; e++) if (acc[e] > b1v) { b1v = acc[e]; b1i = e; }
        int b2i = -1; float b2v = -3.0e38f;
#pragma unroll
        for (int e = 0; e < NEXP; e++)
            if (e != b1i && acc[e] > b2v) { b2v = acc[e]; b2i = e; }
        float p2 = expf(b2v - b1v);
        float inv = 1.f / (1.f + p2);
        g_e1[warp] = b1i; g_e2[warp] = b2i;
        g_w1[warp] = inv; g_w2[warp] = p2 * inv;
        atomicAdd(&g_counts[b1i], 1);
        atomicAdd(&g_counts[b2i], 1);
    }
}

__global__ void k_prefix() {
    if (threadIdx.x == 0 && blockIdx.x == 0) {
        int off = 0;
        for (int e = 0; e < NEXP; e++) {
            g_offsets[e] = off;
            g_cursor[e]  = off;
            off += g_counts[e];
        }
        g_offsets[NEXP] = off;
    }
}

__global__ void k_scatter() {
    int t = blockIdx.x * blockDim.x + threadIdx.x;
    if (t >= NTOK) return;
    int s1 = atomicAdd(&g_cursor[g_e1[t]], 1);
    g_rtok[s1] = t; g_s1[t] = s1;
    int s2 = atomicAdd(&g_cursor[g_e2[t]], 1);
    g_rtok[s2] = t; g_s2[t] = s2;
}

// ---------------- shared tf32 HMMA mainloop ----------------
// smem: A [128 rows][32 k] as 128B swizzled rows (16KB) ; B [128 n][32 k] same (16KB).
// 8 warps: warp tile 64x32 (wm = (wid>>2)*64, wn = (wid&3)*32), mma grid 4x4 of m16n8k8.
template <int NCH, int LDB>
__device__ __forceinline__ void mma_loop(
    uint32_t sA, uint32_t sB,
    const float* __restrict__ a0, const float* __restrict__ a1,
    const float* __restrict__ a2, const float* __restrict__ a3,
    const float* __restrict__ bsrc, int tid, float (&acc)[4][4][4])
{
    const int lanef = tid & 7, rbase = tid >> 3;
    const int kb = (tid & 7) * 4, nb = (tid >> 3) * 4;
    const int lane = tid & 31, wid = tid >> 5;
    const int grp = lane >> 2, tq = lane & 3;
    const int wm = (wid >> 2) * 64, wn = (wid & 3) * 32;

    const float* ap[4] = {a0, a1, a2, a3};
    float4 av[4], bv[4];
#pragma unroll
    for (int j = 0; j < 4; j++) av[j] = *(const float4*)(ap[j]);
#pragma unroll
    for (int r = 0; r < 4; r++) bv[r] = *(const float4*)(bsrc + (size_t)r * LDB);

    for (int i = 0; i < NCH; i++) {
        // ---- STS A (rows rbase+32j, k-group lanef) ----
#pragma unroll
        for (int j = 0; j < 4; j++) {
            uint32_t by = (uint32_t)(rbase + 32 * j) * 128u + (uint32_t)lanef * 16u;
            sts4(sA + SWZ(by), f2tf(av[j].x), f2tf(av[j].y), f2tf(av[j].z), f2tf(av[j].w));
        }
        // ---- STS B: register 4x4 transpose -> [n][k] ----
        {
            uint32_t byn = (uint32_t)nb * 128u + (uint32_t)kb * 4u;
            sts4(sB + SWZ(byn +   0u), f2tf(bv[0].x), f2tf(bv[1].x), f2tf(bv[2].x), f2tf(bv[3].x));
            sts4(sB + SWZ(byn + 128u), f2tf(bv[0].y), f2tf(bv[1].y), f2tf(bv[2].y), f2tf(bv[3].y));
            sts4(sB + SWZ(byn + 256u), f2tf(bv[0].z), f2tf(bv[1].z), f2tf(bv[2].z), f2tf(bv[3].z));
            sts4(sB + SWZ(byn + 384u), f2tf(bv[0].w), f2tf(bv[1].w), f2tf(bv[2].w), f2tf(bv[3].w));
        }
        __syncthreads();

        // ---- prefetch next chunk into registers (hidden under MMA) ----
        if (i + 1 < NCH) {
#pragma unroll
            for (int j = 0; j < 4; j++) av[j] = *(const float4*)(ap[j] + (size_t)(i + 1) * 32);
#pragma unroll
            for (int r = 0; r < 4; r++)
                bv[r] = *(const float4*)(bsrc + (size_t)(i + 1) * 32 * LDB + (size_t)r * LDB);
        }

        // ---- compute 4 k-steps of k8 ----
#pragma unroll
        for (int ks = 0; ks < 4; ks++) {
            uint32_t af[4][4];
#pragma unroll
            for (int ms = 0; ms < 4; ms++) {
                uint32_t m = (uint32_t)(wm + ms * 16 + grp);
                uint32_t k = (uint32_t)(ks * 8 + tq);
                uint32_t b00 = m * 128u + k * 4u;
                af[ms][0] = lds32(sA + SWZ(b00));
                af[ms][1] = lds32(sA + SWZ(b00 + 1024u));        // m+8
                af[ms][2] = lds32(sA + SWZ(b00 + 16u));          // k+4
                af[ms][3] = lds32(sA + SWZ(b00 + 1024u + 16u));
            }
#pragma unroll
            for (int ns = 0; ns < 4; ns++) {
                uint32_t n = (uint32_t)(wn + ns * 8 + grp);
                uint32_t k = (uint32_t)(ks * 8 + tq);
                uint32_t b00 = n * 128u + k * 4u;
                uint32_t b0v = lds32(sB + SWZ(b00));
                uint32_t b1v = lds32(sB + SWZ(b00 + 16u));
#pragma unroll
                for (int ms = 0; ms < 4; ms++)
                    mma_tf32(acc[ms][ns], af[ms], b0v, b1v);
            }
        }
        __syncthreads();
    }
}

// ---------------- GEMM1: h = gelu(x_gathered @ W1[e] + b1[e]) ----------------
__global__ __launch_bounds__(256)
void k_gemm1(const float* __restrict__ x, const float* __restrict__ W1,
             const float* __restrict__ b1) {
    const int e  = blockIdx.z;
    const int off = g_offsets[e];
    const int ne  = g_offsets[e + 1] - off;
    const int m0  = blockIdx.y * 128;
    if (m0 >= ne) return;
    const int n0  = blockIdx.x * 128;

    __shared__ float4 smem[2048];          // 32 KB: A then B
    uint32_t sA = smem_u32(smem);
    uint32_t sB = sA + 16384;

    const int tid = threadIdx.x;
    const int lanef = tid & 7, rbase = tid >> 3;
    const float* ap[4];
#pragma unroll
    for (int j = 0; j < 4; j++) {
        int r = m0 + rbase + 32 * j;
        int tok = g_rtok[off + (r < ne ? r : 0)];
        ap[j] = x + (size_t)tok * CDIM + lanef * 4;
    }
    const float* bsrc = W1 + (size_t)e * CDIM * HDIM +
                        (size_t)((tid & 7) * 4) * HDIM + n0 + (tid >> 3) * 4;

    float acc[4][4][4];
#pragma unroll
    for (int a = 0; a < 4; a++)
#pragma unroll
        for (int b = 0; b < 4; b++)
#pragma unroll
            for (int c = 0; c < 4; c++) acc[a][b][c] = 0.f;

    mma_loop<CDIM / 32, HDIM>(sA, sB, ap[0], ap[1], ap[2], ap[3], bsrc, tid, acc);

    const int lane = tid & 31, wid = tid >> 5;
    const int grp = lane >> 2, tq = lane & 3;
    const int wm = (wid >> 2) * 64, wn = (wid & 3) * 32;
    const float* brow = b1 + (size_t)e * HDIM + n0 + wn;
#pragma unroll
    for (int ms = 0; ms < 4; ms++)
#pragma unroll
        for (int h = 0; h < 2; h++) {
            int r = m0 + wm + ms * 16 + grp + h * 8;
            if (r < ne) {
                float* hrow = g_h + (size_t)(off + r) * HDIM + n0 + wn;
#pragma unroll
                for (int ns = 0; ns < 4; ns++) {
                    int col = ns * 8 + 2 * tq;
                    float2 o;
                    o.x = gelu_exact(acc[ms][ns][h * 2 + 0] + brow[col]);
                    o.y = gelu_exact(acc[ms][ns][h * 2 + 1] + brow[col + 1]);
                    *(float2*)(hrow + col) = o;
                }
            }
        }
}

// ---------------- GEMM2: y = h_slots @ W2[e] + b2[e] ----------------
__global__ __launch_bounds__(256)
void k_gemm2(const float* __restrict__ W2, const float* __restrict__ b2) {
    const int e  = blockIdx.z;
    const int off = g_offsets[e];
    const int ne  = g_offsets[e + 1] - off;
    const int m0  = blockIdx.y * 128;
    if (m0 >= ne) return;
    const int n0  = blockIdx.x * 128;

    __shared__ float4 smem[2048];
    uint32_t sA = smem_u32(smem);
    uint32_t sB = sA + 16384;

    const int tid = threadIdx.x;
    const int lanef = tid & 7, rbase = tid >> 3;
    const float* ap[4];
#pragma unroll
    for (int j = 0; j < 4; j++) {
        int r = m0 + rbase + 32 * j;
        if (r >= ne) r = ne - 1;
        ap[j] = g_h + (size_t)(off + r) * HDIM + lanef * 4;
    }
    const float* bsrc = W2 + (size_t)e * HDIM * CDIM +
                        (size_t)((tid & 7) * 4) * CDIM + n0 + (tid >> 3) * 4;

    float acc[4][4][4];
#pragma unroll
    for (int a = 0; a < 4; a++)
#pragma unroll
        for (int b = 0; b < 4; b++)
#pragma unroll
            for (int c = 0; c < 4; c++) acc[a][b][c] = 0.f;

    mma_loop<HDIM / 32, CDIM>(sA, sB, ap[0], ap[1], ap[2], ap[3], bsrc, tid, acc);

    const int lane = tid & 31, wid = tid >> 5;
    const int grp = lane >> 2, tq = lane & 3;
    const int wm = (wid >> 2) * 64, wn = (wid & 3) * 32;
    const float* brow = b2 + (size_t)e * CDIM + n0 + wn;
#pragma unroll
    for (int ms = 0; ms < 4; ms++)
#pragma unroll
        for (int h = 0; h < 2; h++) {
            int r = m0 + wm + ms * 16 + grp + h * 8;
            if (r < ne) {
                float* yrow = g_y + (size_t)(off + r) * CDIM + n0 + wn;
#pragma unroll
                for (int ns = 0; ns < 4; ns++) {
                    int col = ns * 8 + 2 * tq;
                    float2 o;
                    o.x = acc[ms][ns][h * 2 + 0] + brow[col];
                    o.y = acc[ms][ns][h * 2 + 1] + brow[col + 1];
                    *(float2*)(yrow + col) = o;
                }
            }
        }
}

// ---------------- combine: out[t] = w1*y[s1] + w2*y[s2] ----------------
__global__ void k_combine(float* __restrict__ out) {
    int t = blockIdx.x;
    int c = threadIdx.x * 4;
    float w1 = g_w1[t], w2 = g_w2[t];
    const float4 a = *(const float4*)(g_y + (size_t)g_s1[t] * CDIM + c);
    const float4 b = *(const float4*)(g_y + (size_t)g_s2[t] * CDIM + c);
    float4 o;
    o.x = w1 * a.x + w2 * b.x;
    o.y = w1 * a.y + w2 * b.y;
    o.z = w1 * a.z + w2 * b.z;
    o.w = w1 * a.w + w2 * b.w;
    *(float4*)(out + (size_t)t * CDIM + c) = o;
}

extern "C" void kernel_launch(void* const* d_in, const int* in_sizes, int n_in,
                              void* d_out, int out_size) {
    const float* x  = (const float*)d_in[0];
    const float* Wg = (const float*)d_in[1];
    const float* bg = (const float*)d_in[2];
    const float* W1 = (const float*)d_in[3];
    const float* b1 = (const float*)d_in[4];
    const float* W2 = (const float*)d_in[5];
    const float* b2 = (const float*)d_in[6];
    float* out = (float*)d_out;

    k_init<<<1, 32>>>();
    k_gate<<<(NTOK * 32 + 255) / 256, 256>>>(x, Wg, bg);
    k_prefix<<<1, 1>>>();
    k_scatter<<<(NTOK + 255) / 256, 256>>>();

    dim3 grd1(HDIM / 128, 32, NEXP);   // worst-case M tiles; empty tiles exit early
    k_gemm1<<<grd1, 256>>>(x, W1, b1);
    dim3 grd2(CDIM / 128, 32, NEXP);
    k_gemm2<<<grd2, 256>>>(W2, b2);
    k_combine<<<NTOK, 256>>>(out);
}

// round 6
// speedup vs baseline: 2.6768x; 1.2703x over previous
#include <cuda_runtime.h>
#include <math.h>
#include <stdint.h>

#define NTOK 4096
#define CDIM 1024
#define HDIM 4096
#define NEXP 8
#define NSLOT (NTOK * 2)

// GEMM geometry: block tile 256(M) x 128(N) x 32(K), 8 warps of 64x64
#define STAGE_BYTES 49152            // A 32KB + B 16KB
#define SMEM_BYTES  (3 * STAGE_BYTES)

// ---------------- static device scratch ----------------
__device__ int g_counts[NEXP];
__device__ int g_offsets[NEXP + 1];
__device__ int g_cursor[NEXP];
__device__ __align__(16) int g_rtok[NSLOT];
__device__ int g_e1[NTOK], g_e2[NTOK];
__device__ int g_s1[NTOK], g_s2[NTOK];
__device__ float g_w1[NTOK], g_w2[NTOK];
__device__ __align__(256) float g_h[(size_t)NSLOT * HDIM];   // 128 MiB
__device__ __align__(256) float g_y[(size_t)NSLOT * CDIM];   // 32 MiB

// ---------------- helpers ----------------
__device__ __forceinline__ uint32_t smem_u32(const void* p) {
    uint32_t a;
    asm("{ .reg .u64 t; cvta.to.shared.u64 t, %1; cvt.u32.u64 %0, t; }" : "=r"(a) : "l"(p));
    return a;
}
__device__ __forceinline__ uint32_t f2tf(float f) {
    uint32_t r; asm("cvt.rna.tf32.f32 %0, %1;" : "=r"(r) : "f"(f)); return r;
}
#define SWZ(o) ((o) ^ ((((uint32_t)(o)) >> 3) & 0x70u))

__device__ __forceinline__ void sts4(uint32_t a, uint32_t x, uint32_t y, uint32_t z, uint32_t w) {
    asm volatile("st.shared.v4.b32 [%0], {%1,%2,%3,%4};" :: "r"(a), "r"(x), "r"(y), "r"(z), "r"(w) : "memory");
}
__device__ __forceinline__ uint32_t lds32(uint32_t a) {
    uint32_t v; asm volatile("ld.shared.b32 %0, [%1];" : "=r"(v) : "r"(a)); return v;
}
__device__ __forceinline__ void cp16(uint32_t dst, const void* src) {
    asm volatile("cp.async.cg.shared.global [%0], [%1], 16;" :: "r"(dst), "l"(src) : "memory");
}
__device__ __forceinline__ void mma_tf32(float* c, const uint32_t a[4], uint32_t b0, uint32_t b1) {
    asm volatile(
        "mma.sync.aligned.m16n8k8.row.col.f32.tf32.tf32.f32 "
        "{%0,%1,%2,%3}, {%4,%5,%6,%7}, {%8,%9}, {%0,%1,%2,%3};"
        : "+f"(c[0]), "+f"(c[1]), "+f"(c[2]), "+f"(c[3])
        : "r"(a[0]), "r"(a[1]), "r"(a[2]), "r"(a[3]), "r"(b0), "r"(b1));
}
__device__ __forceinline__ float gelu_exact(float v) {
    return 0.5f * v * (1.0f + erff(v * 0.70710678118654752f));
}

// ---------------- routing kernels ----------------
__global__ void k_init() {
    int t = threadIdx.x;
    if (t < NEXP) g_counts[t] = 0;
}

__global__ void k_gate(const float* __restrict__ x, const float* __restrict__ Wg,
                       const float* __restrict__ bg) {
    int warp = (blockIdx.x * blockDim.x + threadIdx.x) >> 5;
    int lane = threadIdx.x & 31;
    if (warp >= NTOK) return;
    const float* xr = x + (size_t)warp * CDIM;
    float acc[NEXP];
#pragma unroll
    for (int e = 0; e < NEXP; e++) acc[e] = 0.f;
    for (int k = lane; k < CDIM; k += 32) {
        float xv = xr[k];
        const float* wr = Wg + k * NEXP;
#pragma unroll
        for (int e = 0; e < NEXP; e++) acc[e] = fmaf(xv, wr[e], acc[e]);
    }
#pragma unroll
    for (int off = 16; off; off >>= 1)
#pragma unroll
        for (int e = 0; e < NEXP; e++)
            acc[e] += __shfl_xor_sync(0xffffffffu, acc[e], off);
    if (lane == 0) {
#pragma unroll
        for (int e = 0; e < NEXP; e++) acc[e] += bg[e];
        int b1i = 0; float b1v = acc[0];
#pragma unroll
        for (int e = 1; e < NEXP; e++) if (acc[e] > b1v) { b1v = acc[e]; b1i = e; }
        int b2i = -1; float b2v = -3.0e38f;
#pragma unroll
        for (int e = 0; e < NEXP; e++)
            if (e != b1i && acc[e] > b2v) { b2v = acc[e]; b2i = e; }
        float p2 = expf(b2v - b1v);
        float inv = 1.f / (1.f + p2);
        g_e1[warp] = b1i; g_e2[warp] = b2i;
        g_w1[warp] = inv; g_w2[warp] = p2 * inv;
        atomicAdd(&g_counts[b1i], 1);
        atomicAdd(&g_counts[b2i], 1);
    }
}

__global__ void k_prefix() {
    if (threadIdx.x == 0 && blockIdx.x == 0) {
        int off = 0;
        for (int e = 0; e < NEXP; e++) {
            g_offsets[e] = off;
            g_cursor[e]  = off;
            off += g_counts[e];
        }
        g_offsets[NEXP] = off;
    }
}

__global__ void k_scatter() {
    int t = blockIdx.x * blockDim.x + threadIdx.x;
    if (t >= NTOK) return;
    int s1 = atomicAdd(&g_cursor[g_e1[t]], 1);
    g_rtok[s1] = t; g_s1[t] = s1;
    int s2 = atomicAdd(&g_cursor[g_e2[t]], 1);
    g_rtok[s2] = t; g_s2[t] = s2;
}

// ---------------- tf32 HMMA mainloop (256x128 tile, 3-stage pipeline) ----------------
// smem stage: A [256 rows][32 k] swizzled 128B rows (32KB), B [128 n][32 k] (16KB).
// 8 warps as 4(m) x 2(n): warp tile 64x64; ms 0..3 (m16), ns 0..7 (n8).
template <int NCH, int LDB>
__device__ __forceinline__ void mma_loop(
    uint32_t sb, const float* const (&ap)[8], const float* bsrc,
    int tid, float (&acc)[4][8][4])
{
    const int lane = tid & 31, wid = tid >> 5;
    const int grp = lane >> 2, tq = lane & 3;
    const int wm = (wid >> 1) * 64, wn = (wid & 1) * 64;
    const int lanef = tid & 7, rbase = tid >> 3;
    const int kb = (tid & 7) * 4, nb = (tid >> 3) * 4;

    uint32_t adst[8];
#pragma unroll
    for (int j = 0; j < 8; j++)
        adst[j] = SWZ((uint32_t)(rbase + 32 * j) * 128u + (uint32_t)lanef * 16u);

    float4 bv[4];

#define LDG_B(ch)                                                                     \
    {                                                                                 \
        const float* bp = bsrc + (size_t)(ch) * 32 * LDB;                             \
        bv[0] = *(const float4*)(bp);                                                 \
        bv[1] = *(const float4*)(bp + LDB);                                           \
        bv[2] = *(const float4*)(bp + 2 * LDB);                                       \
        bv[3] = *(const float4*)(bp + 3 * LDB);                                       \
    }
#define STS_B(s)                                                                      \
    {                                                                                 \
        uint32_t Bb = sb + (uint32_t)(s) * STAGE_BYTES + 32768u;                      \
        uint32_t byn = (uint32_t)nb * 128u + (uint32_t)kb * 4u;                       \
        sts4(Bb + SWZ(byn +   0u), f2tf(bv[0].x), f2tf(bv[1].x), f2tf(bv[2].x), f2tf(bv[3].x)); \
        sts4(Bb + SWZ(byn + 128u), f2tf(bv[0].y), f2tf(bv[1].y), f2tf(bv[2].y), f2tf(bv[3].y)); \
        sts4(Bb + SWZ(byn + 256u), f2tf(bv[0].z), f2tf(bv[1].z), f2tf(bv[2].z), f2tf(bv[3].z)); \
        sts4(Bb + SWZ(byn + 384u), f2tf(bv[0].w), f2tf(bv[1].w), f2tf(bv[2].w), f2tf(bv[3].w)); \
    }
#define CP_A(ch, s)                                                                   \
    {                                                                                 \
        uint32_t Ab = sb + (uint32_t)(s) * STAGE_BYTES;                               \
_Pragma("unroll")                                                                     \
        for (int j = 0; j < 8; j++)                                                   \
            cp16(Ab + adst[j], ap[j] + (size_t)(ch) * 32);                            \
    }

    // ---- prologue: chunks 0,1 into stages 0,1 ----
    LDG_B(0); STS_B(0); CP_A(0, 0);
    asm volatile("cp.async.commit_group;" ::: "memory");
    LDG_B(1); CP_A(1, 1);
    asm volatile("cp.async.commit_group;" ::: "memory");
    STS_B(1);

    for (int i = 0; i < NCH; i++) {
        const int s2 = (i + 2) % 3;
        const bool pf = (i + 2) < NCH;
        if (pf) LDG_B(i + 2);
        asm volatile("cp.async.wait_group 1;" ::: "memory");
        __syncthreads();
        if (pf) CP_A(i + 2, s2);
        asm volatile("cp.async.commit_group;" ::: "memory");

        // compute chunk i from stage i%3
        uint32_t Ab = sb + (uint32_t)(i % 3) * STAGE_BYTES;
        uint32_t Bb = Ab + 32768u;
#pragma unroll
        for (int ks = 0; ks < 4; ks++) {
            uint32_t bq[8][2];
#pragma unroll
            for (int ns = 0; ns < 8; ns++) {
                uint32_t n = (uint32_t)(wn + ns * 8 + grp);
                uint32_t b00 = n * 128u + (uint32_t)(ks * 8 + tq) * 4u;
                bq[ns][0] = lds32(Bb + SWZ(b00));
                bq[ns][1] = lds32(Bb + SWZ(b00 + 16u));
            }
#pragma unroll
            for (int ms = 0; ms < 4; ms++) {
                uint32_t m = (uint32_t)(wm + ms * 16 + grp);
                uint32_t a00 = m * 128u + (uint32_t)(ks * 8 + tq) * 4u;
                uint32_t af[4];
                af[0] = lds32(Ab + SWZ(a00));
                af[1] = lds32(Ab + SWZ(a00 + 1024u));
                af[2] = lds32(Ab + SWZ(a00 + 16u));
                af[3] = lds32(Ab + SWZ(a00 + 1024u + 16u));
#pragma unroll
                for (int ns = 0; ns < 8; ns++)
                    mma_tf32(acc[ms][ns], af, bq[ns][0], bq[ns][1]);
            }
        }
        if (pf) STS_B(s2);
    }
#undef LDG_B
#undef STS_B
#undef CP_A
}

// ---------------- GEMM1: h = gelu(x_gathered @ W1[e] + b1[e]) ----------------
__global__ __launch_bounds__(256)
void k_gemm1(const float* __restrict__ x, const float* __restrict__ W1,
             const float* __restrict__ b1) {
    const int e  = blockIdx.z;
    const int off = g_offsets[e];
    const int ne  = g_offsets[e + 1] - off;
    const int m0  = blockIdx.y * 256;
    if (m0 >= ne) return;
    const int n0  = blockIdx.x * 128;

    extern __shared__ __align__(1024) char smem[];
    uint32_t sb = smem_u32(smem);
    const int tid = threadIdx.x;
    const int lanef = tid & 7, rbase = tid >> 3;

    const float* ap[8];
#pragma unroll
    for (int j = 0; j < 8; j++) {
        int r = m0 + rbase + 32 * j;
        int tok = g_rtok[off + (r < ne ? r : 0)];
        ap[j] = x + (size_t)tok * CDIM + lanef * 4;
    }
    const float* bsrc = W1 + (size_t)e * CDIM * HDIM +
                        (size_t)((tid & 7) * 4) * HDIM + n0 + (tid >> 3) * 4;

    float acc[4][8][4];
#pragma unroll
    for (int a = 0; a < 4; a++)
#pragma unroll
        for (int b = 0; b < 8; b++)
#pragma unroll
            for (int c = 0; c < 4; c++) acc[a][b][c] = 0.f;

    mma_loop<CDIM / 32, HDIM>(sb, ap, bsrc, tid, acc);

    const int lane = tid & 31, wid = tid >> 5;
    const int grp = lane >> 2, tq = lane & 3;
    const int wm = (wid >> 1) * 64, wn = (wid & 1) * 64;
    const float* brow = b1 + (size_t)e * HDIM + n0 + wn;
#pragma unroll
    for (int ms = 0; ms < 4; ms++)
#pragma unroll
        for (int h = 0; h < 2; h++) {
            int r = m0 + wm + ms * 16 + grp + h * 8;
            if (r < ne) {
                float* hrow = g_h + (size_t)(off + r) * HDIM + n0 + wn;
#pragma unroll
                for (int ns = 0; ns < 8; ns++) {
                    int col = ns * 8 + 2 * tq;
                    float2 o;
                    // pre-round to tf32 so gemm2's raw-bit A operand is RNA-rounded
                    o.x = __uint_as_float(f2tf(gelu_exact(acc[ms][ns][h * 2 + 0] + brow[col])));
                    o.y = __uint_as_float(f2tf(gelu_exact(acc[ms][ns][h * 2 + 1] + brow[col + 1])));
                    *(float2*)(hrow + col) = o;
                }
            }
        }
}

// ---------------- GEMM2: y = h_slots @ W2[e] + b2[e] ----------------
__global__ __launch_bounds__(256)
void k_gemm2(const float* __restrict__ W2, const float* __restrict__ b2) {
    const int e  = blockIdx.z;
    const int off = g_offsets[e];
    const int ne  = g_offsets[e + 1] - off;
    const int m0  = blockIdx.y * 256;
    if (m0 >= ne) return;
    const int n0  = blockIdx.x * 128;

    extern __shared__ __align__(1024) char smem[];
    uint32_t sb = smem_u32(smem);
    const int tid = threadIdx.x;
    const int lanef = tid & 7, rbase = tid >> 3;

    const float* ap[8];
#pragma unroll
    for (int j = 0; j < 8; j++) {
        int r = m0 + rbase + 32 * j;
        if (r >= ne) r = ne - 1;
        ap[j] = g_h + (size_t)(off + r) * HDIM + lanef * 4;
    }
    const float* bsrc = W2 + (size_t)e * HDIM * CDIM +
                        (size_t)((tid & 7) * 4) * CDIM + n0 + (tid >> 3) * 4;

    float acc[4][8][4];
#pragma unroll
    for (int a = 0; a < 4; a++)
#pragma unroll
        for (int b = 0; b < 8; b++)
#pragma unroll
            for (int c = 0; c < 4; c++) acc[a][b][c] = 0.f;

    mma_loop<HDIM / 32, CDIM>(sb, ap, bsrc, tid, acc);

    const int lane = tid & 31, wid = tid >> 5;
    const int grp = lane >> 2, tq = lane & 3;
    const int wm = (wid >> 1) * 64, wn = (wid & 1) * 64;
    const float* brow = b2 + (size_t)e * CDIM + n0 + wn;
#pragma unroll
    for (int ms = 0; ms < 4; ms++)
#pragma unroll
        for (int h = 0; h < 2; h++) {
            int r = m0 + wm + ms * 16 + grp + h * 8;
            if (r < ne) {
                float* yrow = g_y + (size_t)(off + r) * CDIM + n0 + wn;
#pragma unroll
                for (int ns = 0; ns < 8; ns++) {
                    int col = ns * 8 + 2 * tq;
                    float2 o;
                    o.x = acc[ms][ns][h * 2 + 0] + brow[col];
                    o.y = acc[ms][ns][h * 2 + 1] + brow[col + 1];
                    *(float2*)(yrow + col) = o;
                }
            }
        }
}

// ---------------- combine: out[t] = w1*y[s1] + w2*y[s2] ----------------
__global__ void k_combine(float* __restrict__ out) {
    int t = blockIdx.x;
    int c = threadIdx.x * 4;
    float w1 = g_w1[t], w2 = g_w2[t];
    const float4 a = *(const float4*)(g_y + (size_t)g_s1[t] * CDIM + c);
    const float4 b = *(const float4*)(g_y + (size_t)g_s2[t] * CDIM + c);
    float4 o;
    o.x = w1 * a.x + w2 * b.x;
    o.y = w1 * a.y + w2 * b.y;
    o.z = w1 * a.z + w2 * b.z;
    o.w = w1 * a.w + w2 * b.w;
    *(float4*)(out + (size_t)t * CDIM + c) = o;
}

extern "C" void kernel_launch(void* const* d_in, const int* in_sizes, int n_in,
                              void* d_out, int out_size) {
    const float* x  = (const float*)d_in[0];
    const float* Wg = (const float*)d_in[1];
    const float* bg = (const float*)d_in[2];
    const float* W1 = (const float*)d_in[3];
    const float* b1 = (const float*)d_in[4];
    const float* W2 = (const float*)d_in[5];
    const float* b2 = (const float*)d_in[6];
    float* out = (float*)d_out;

    cudaFuncSetAttribute(k_gemm1, cudaFuncAttributeMaxDynamicSharedMemorySize, SMEM_BYTES);
    cudaFuncSetAttribute(k_gemm2, cudaFuncAttributeMaxDynamicSharedMemorySize, SMEM_BYTES);

    k_init<<<1, 32>>>();
    k_gate<<<(NTOK * 32 + 255) / 256, 256>>>(x, Wg, bg);
    k_prefix<<<1, 1>>>();
    k_scatter<<<(NTOK + 255) / 256, 256>>>();

    dim3 grd1(HDIM / 128, 16, NEXP);   // worst-case M tiles (ne<=4096); empty tiles exit early
    k_gemm1<<<grd1, 256, SMEM_BYTES>>>(x, W1, b1);
    dim3 grd2(CDIM / 128, 16, NEXP);
    k_gemm2<<<grd2, 256, SMEM_BYTES>>>(W2, b2);
    k_combine<<<NTOK, 256>>>(out);
}

// round 7
// speedup vs baseline: 6.0551x; 2.2621x over previous
#include <cuda_runtime.h>
#include <cuda_fp16.h>
#include <math.h>
#include <stdint.h>

#define NTOK 4096
#define CDIM 1024
#define HDIM 4096
#define NEXP 8
#define NSLOT (NTOK * 2)

// GEMM geometry: block tile 256(M) x 128(N) x 64(K) fp16, 8 warps of 64x64
#define STAGE_BYTES 49152            // A 32KB + B 16KB
#define SMEM_BYTES  (3 * STAGE_BYTES)

// ---------------- static device scratch ----------------
__device__ int g_counts[NEXP];
__device__ int g_offsets[NEXP + 1];
__device__ int g_cursor[NEXP];
__device__ __align__(16) int g_rtok[NSLOT];
__device__ int g_e1[NTOK], g_e2[NTOK];
__device__ int g_s1[NTOK], g_s2[NTOK];
__device__ float g_w1[NTOK], g_w2[NTOK];
__device__ __align__(256) __half g_x16[(size_t)NTOK * CDIM];          // 8 MiB
__device__ __align__(256) __half g_w1h[(size_t)NEXP * CDIM * HDIM];   // 64 MiB
__device__ __align__(256) __half g_w2h[(size_t)NEXP * HDIM * CDIM];   // 64 MiB
__device__ __align__(256) __half g_h[(size_t)NSLOT * HDIM];           // 64 MiB
__device__ __align__(256) float  g_y[(size_t)NSLOT * CDIM];           // 32 MiB

// ---------------- helpers ----------------
__device__ __forceinline__ uint32_t smem_u32(const void* p) {
    uint32_t a;
    asm("{ .reg .u64 t; cvta.to.shared.u64 t, %1; cvt.u32.u64 %0, t; }" : "=r"(a) : "l"(p));
    return a;
}
#define SWZ(o)    ((o) ^ ((((uint32_t)(o)) >> 3) & 0x70u))   // 128B rows
#define SWZ256(o) ((o) ^ ((((uint32_t)(o)) >> 4) & 0x70u))   // 256B rows

__device__ __forceinline__ void cp16(uint32_t dst, const void* src) {
    asm volatile("cp.async.cg.shared.global [%0], [%1], 16;" :: "r"(dst), "l"(src) : "memory");
}
__device__ __forceinline__ void ldsm4(uint32_t& r0, uint32_t& r1, uint32_t& r2, uint32_t& r3, uint32_t a) {
    asm volatile("ldmatrix.sync.aligned.m8n8.x4.shared.b16 {%0,%1,%2,%3}, [%4];"
                 : "=r"(r0), "=r"(r1), "=r"(r2), "=r"(r3) : "r"(a));
}
__device__ __forceinline__ void ldsm4t(uint32_t& r0, uint32_t& r1, uint32_t& r2, uint32_t& r3, uint32_t a) {
    asm volatile("ldmatrix.sync.aligned.m8n8.x4.trans.shared.b16 {%0,%1,%2,%3}, [%4];"
                 : "=r"(r0), "=r"(r1), "=r"(r2), "=r"(r3) : "r"(a));
}
__device__ __forceinline__ void mma_f16(float* c, uint32_t a0, uint32_t a1, uint32_t a2, uint32_t a3,
                                        uint32_t b0, uint32_t b1) {
    asm volatile(
        "mma.sync.aligned.m16n8k16.row.col.f32.f16.f16.f32 "
        "{%0,%1,%2,%3}, {%4,%5,%6,%7}, {%8,%9}, {%0,%1,%2,%3};"
        : "+f"(c[0]), "+f"(c[1]), "+f"(c[2]), "+f"(c[3])
        : "r"(a0), "r"(a1), "r"(a2), "r"(a3), "r"(b0), "r"(b1));
}
__device__ __forceinline__ float gelu_exact(float v) {
    return 0.5f * v * (1.0f + erff(v * 0.70710678118654752f));
}

// ---------------- fp32 -> fp16 convert ----------------
__global__ void k_cvt(const float4* __restrict__ src, uint2* __restrict__ dst, int n4) {
    int i = blockIdx.x * blockDim.x + threadIdx.x;
    if (i < n4) {
        float4 v = src[i];
        __half2 lo = __floats2half2_rn(v.x, v.y);
        __half2 hi = __floats2half2_rn(v.z, v.w);
        uint2 o;
        o.x = *(uint32_t*)&lo;
        o.y = *(uint32_t*)&hi;
        dst[i] = o;
    }
}

// ---------------- routing kernels ----------------
__global__ void k_init() {
    int t = threadIdx.x;
    if (t < NEXP) g_counts[t] = 0;
}

__global__ void k_gate(const float* __restrict__ x, const float* __restrict__ Wg,
                       const float* __restrict__ bg) {
    int warp = (blockIdx.x * blockDim.x + threadIdx.x) >> 5;
    int lane = threadIdx.x & 31;
    if (warp >= NTOK) return;
    const float* xr = x + (size_t)warp * CDIM;
    float acc[NEXP];
#pragma unroll
    for (int e = 0; e < NEXP; e++) acc[e] = 0.f;
    for (int k = lane; k < CDIM; k += 32) {
        float xv = xr[k];
        const float* wr = Wg + k * NEXP;
#pragma unroll
        for (int e = 0; e < NEXP; e++) acc[e] = fmaf(xv, wr[e], acc[e]);
    }
#pragma unroll
    for (int off = 16; off; off >>= 1)
#pragma unroll
        for (int e = 0; e < NEXP; e++)
            acc[e] += __shfl_xor_sync(0xffffffffu, acc[e], off);
    if (lane == 0) {
#pragma unroll
        for (int e = 0; e < NEXP; e++) acc[e] += bg[e];
        int b1i = 0; float b1v = acc[0];
#pragma unroll
        for (int e = 1; e < NEXP; e++) if (acc[e] > b1v) { b1v = acc[e]; b1i = e; }
        int b2i = -1; float b2v = -3.0e38f;
#pragma unroll
        for (int e = 0; e < NEXP; e++)
            if (e != b1i && acc[e] > b2v) { b2v = acc[e]; b2i = e; }
        float p2 = expf(b2v - b1v);
        float inv = 1.f / (1.f + p2);
        g_e1[warp] = b1i; g_e2[warp] = b2i;
        g_w1[warp] = inv; g_w2[warp] = p2 * inv;
        atomicAdd(&g_counts[b1i], 1);
        atomicAdd(&g_counts[b2i], 1);
    }
}

__global__ void k_prefix() {
    if (threadIdx.x == 0 && blockIdx.x == 0) {
        int off = 0;
        for (int e = 0; e < NEXP; e++) {
            g_offsets[e] = off;
            g_cursor[e]  = off;
            off += g_counts[e];
        }
        g_offsets[NEXP] = off;
    }
}

__global__ void k_scatter() {
    int t = blockIdx.x * blockDim.x + threadIdx.x;
    if (t >= NTOK) return;
    int s1 = atomicAdd(&g_cursor[g_e1[t]], 1);
    g_rtok[s1] = t; g_s1[t] = s1;
    int s2 = atomicAdd(&g_cursor[g_e2[t]], 1);
    g_rtok[s2] = t; g_s2[t] = s2;
}

// ---------------- fp16 HMMA mainloop (256x128x64, 3-stage cp.async pipeline) ----------------
// Stage: A [256 m][64 k] fp16 swizzled 128B rows (32KB); B [64 k][128 n] fp16 swizzled 256B rows (16KB).
// 8 warps as 4(m) x 2(n): warp tile 64x64; ms 0..3 (m16), ns 0..7 (n8), ks 0..3 (k16).
template <int NCH>
__device__ __forceinline__ void mma_loop(
    uint32_t sb, const __half* const (&ap)[8], const __half* bsrc, int ldb,
    int tid, float (&acc)[4][8][4])
{
    const int lane = tid & 31, wid = tid >> 5;
    const int wm = (wid >> 1) * 64, wn = (wid & 1) * 64;

    uint32_t adst[8];
#pragma unroll
    for (int j = 0; j < 8; j++)
        adst[j] = SWZ((uint32_t)((tid >> 3) + 32 * j) * 128u + (uint32_t)(tid & 7) * 16u);
    uint32_t bdst[4];
#pragma unroll
    for (int j = 0; j < 4; j++)
        bdst[j] = 32768u + SWZ256((uint32_t)((tid >> 4) + 16 * j) * 256u + (uint32_t)(tid & 15) * 16u);

#define CPS(ch, s)                                                                    \
    {                                                                                 \
        uint32_t base = sb + (uint32_t)(s) * STAGE_BYTES;                             \
_Pragma("unroll")                                                                     \
        for (int j = 0; j < 8; j++)                                                   \
            cp16(base + adst[j], ap[j] + (size_t)(ch) * 64);                          \
_Pragma("unroll")                                                                     \
        for (int j = 0; j < 4; j++)                                                   \
            cp16(base + bdst[j], bsrc + ((size_t)(ch) * 64 + 16 * j) * ldb);          \
    }

    CPS(0, 0);
    asm volatile("cp.async.commit_group;" ::: "memory");
    CPS(1, 1);
    asm volatile("cp.async.commit_group;" ::: "memory");

    for (int i = 0; i < NCH; i++) {
        const bool pf = (i + 2) < NCH;
        asm volatile("cp.async.wait_group 1;" ::: "memory");
        __syncthreads();
        if (pf) CPS(i + 2, (i + 2) % 3);
        asm volatile("cp.async.commit_group;" ::: "memory");

        uint32_t As = sb + (uint32_t)(i % 3) * STAGE_BYTES;
        uint32_t Bb = As + 32768u;
#pragma unroll
        for (int ks = 0; ks < 4; ks++) {
            uint32_t bq[8][2];
#pragma unroll
            for (int p = 0; p < 4; p++) {
                int g = lane >> 3, r = lane & 7;
                uint32_t krow = (uint32_t)(ks * 16 + (g & 1) * 8 + r);
                uint32_t nby  = (uint32_t)(wn + p * 16 + (g >> 1) * 8) * 2u;
                uint32_t addr = Bb + SWZ256(krow * 256u + nby);
                ldsm4t(bq[2 * p][0], bq[2 * p][1], bq[2 * p + 1][0], bq[2 * p + 1][1], addr);
            }
#pragma unroll
            for (int ms = 0; ms < 4; ms++) {
                uint32_t row  = (uint32_t)(wm + ms * 16 + (lane & 15));
                uint32_t colb = (uint32_t)(ks * 32 + (lane >> 4) * 16);
                uint32_t addr = As + SWZ(row * 128u + colb);
                uint32_t a0, a1, a2, a3;
                ldsm4(a0, a1, a2, a3, addr);
#pragma unroll
                for (int ns = 0; ns < 8; ns++)
                    mma_f16(acc[ms][ns], a0, a1, a2, a3, bq[ns][0], bq[ns][1]);
            }
        }
    }
#undef CPS
}

// ---------------- GEMM1: h = gelu(x16_gathered @ W1h[e] + b1[e]) ----------------
__global__ __launch_bounds__(256)
void k_gemm1(const float* __restrict__ b1) {
    const int e  = blockIdx.z;
    const int off = g_offsets[e];
    const int ne  = g_offsets[e + 1] - off;
    const int m0  = blockIdx.y * 256;
    if (m0 >= ne) return;
    const int n0  = blockIdx.x * 128;

    extern __shared__ __align__(1024) char smem[];
    uint32_t sb = smem_u32(smem);
    const int tid = threadIdx.x;

    const __half* ap[8];
#pragma unroll
    for (int j = 0; j < 8; j++) {
        int r = m0 + (tid >> 3) + 32 * j;
        int tok = g_rtok[off + (r < ne ? r : 0)];
        ap[j] = g_x16 + (size_t)tok * CDIM + (tid & 7) * 8;
    }
    const __half* bsrc = g_w1h + (size_t)e * CDIM * HDIM +
                         (size_t)(tid >> 4) * HDIM + n0 + (tid & 15) * 8;

    float acc[4][8][4];
#pragma unroll
    for (int a = 0; a < 4; a++)
#pragma unroll
        for (int b = 0; b < 8; b++)
#pragma unroll
            for (int c = 0; c < 4; c++) acc[a][b][c] = 0.f;

    mma_loop<CDIM / 64>(sb, ap, bsrc, HDIM, tid, acc);

    const int lane = tid & 31, wid = tid >> 5;
    const int grp = lane >> 2, tq = lane & 3;
    const int wm = (wid >> 1) * 64, wn = (wid & 1) * 64;
    const float* brow = b1 + (size_t)e * HDIM + n0 + wn;
#pragma unroll
    for (int ms = 0; ms < 4; ms++)
#pragma unroll
        for (int h = 0; h < 2; h++) {
            int r = m0 + wm + ms * 16 + grp + h * 8;
            if (r < ne) {
                __half* hrow = g_h + (size_t)(off + r) * HDIM + n0 + wn;
#pragma unroll
                for (int ns = 0; ns < 8; ns++) {
                    int col = ns * 8 + 2 * tq;
                    __half2 o = __floats2half2_rn(
                        gelu_exact(acc[ms][ns][h * 2 + 0] + brow[col]),
                        gelu_exact(acc[ms][ns][h * 2 + 1] + brow[col + 1]));
                    *(__half2*)(hrow + col) = o;
                }
            }
        }
}

// ---------------- GEMM2: y = h_slots @ W2h[e] + b2[e] ----------------
__global__ __launch_bounds__(256)
void k_gemm2(const float* __restrict__ b2) {
    const int e  = blockIdx.z;
    const int off = g_offsets[e];
    const int ne  = g_offsets[e + 1] - off;
    const int m0  = blockIdx.y * 256;
    if (m0 >= ne) return;
    const int n0  = blockIdx.x * 128;

    extern __shared__ __align__(1024) char smem[];
    uint32_t sb = smem_u32(smem);
    const int tid = threadIdx.x;

    const __half* ap[8];
#pragma unroll
    for (int j = 0; j < 8; j++) {
        int r = m0 + (tid >> 3) + 32 * j;
        if (r >= ne) r = ne - 1;
        ap[j] = g_h + (size_t)(off + r) * HDIM + (tid & 7) * 8;
    }
    const __half* bsrc = g_w2h + (size_t)e * HDIM * CDIM +
                         (size_t)(tid >> 4) * CDIM + n0 + (tid & 15) * 8;

    float acc[4][8][4];
#pragma unroll
    for (int a = 0; a < 4; a++)
#pragma unroll
        for (int b = 0; b < 8; b++)
#pragma unroll
            for (int c = 0; c < 4; c++) acc[a][b][c] = 0.f;

    mma_loop<HDIM / 64>(sb, ap, bsrc, CDIM, tid, acc);

    const int lane = tid & 31, wid = tid >> 5;
    const int grp = lane >> 2, tq = lane & 3;
    const int wm = (wid >> 1) * 64, wn = (wid & 1) * 64;
    const float* brow = b2 + (size_t)e * CDIM + n0 + wn;
#pragma unroll
    for (int ms = 0; ms < 4; ms++)
#pragma unroll
        for (int h = 0; h < 2; h++) {
            int r = m0 + wm + ms * 16 + grp + h * 8;
            if (r < ne) {
                float* yrow = g_y + (size_t)(off + r) * CDIM + n0 + wn;
#pragma unroll
                for (int ns = 0; ns < 8; ns++) {
                    int col = ns * 8 + 2 * tq;
                    float2 o;
                    o.x = acc[ms][ns][h * 2 + 0] + brow[col];
                    o.y = acc[ms][ns][h * 2 + 1] + brow[col + 1];
                    *(float2*)(yrow + col) = o;
                }
            }
        }
}

// ---------------- combine: out[t] = w1*y[s1] + w2*y[s2] ----------------
__global__ void k_combine(float* __restrict__ out) {
    int t = blockIdx.x;
    int c = threadIdx.x * 4;
    float w1 = g_w1[t], w2 = g_w2[t];
    const float4 a = *(const float4*)(g_y + (size_t)g_s1[t] * CDIM + c);
    const float4 b = *(const float4*)(g_y + (size_t)g_s2[t] * CDIM + c);
    float4 o;
    o.x = w1 * a.x + w2 * b.x;
    o.y = w1 * a.y + w2 * b.y;
    o.z = w1 * a.z + w2 * b.z;
    o.w = w1 * a.w + w2 * b.w;
    *(float4*)(out + (size_t)t * CDIM + c) = o;
}

extern "C" void kernel_launch(void* const* d_in, const int* in_sizes, int n_in,
                              void* d_out, int out_size) {
    const float* x  = (const float*)d_in[0];
    const float* Wg = (const float*)d_in[1];
    const float* bg = (const float*)d_in[2];
    const float* W1 = (const float*)d_in[3];
    const float* b1 = (const float*)d_in[4];
    const float* W2 = (const float*)d_in[5];
    const float* b2 = (const float*)d_in[6];
    float* out = (float*)d_out;

    cudaFuncSetAttribute(k_gemm1, cudaFuncAttributeMaxDynamicSharedMemorySize, SMEM_BYTES);
    cudaFuncSetAttribute(k_gemm2, cudaFuncAttributeMaxDynamicSharedMemorySize, SMEM_BYTES);

    __half* x16p;  cudaGetSymbolAddress((void**)&x16p, g_x16);
    __half* w1hp;  cudaGetSymbolAddress((void**)&w1hp, g_w1h);
    __half* w2hp;  cudaGetSymbolAddress((void**)&w2hp, g_w2h);

    const int nx4 = NTOK * CDIM / 4;
    const int nw4 = NEXP * CDIM * HDIM / 4;
    k_cvt<<<(nx4 + 255) / 256, 256>>>((const float4*)x, (uint2*)x16p, nx4);
    k_cvt<<<(nw4 + 255) / 256, 256>>>((const float4*)W1, (uint2*)w1hp, nw4);
    k_cvt<<<(nw4 + 255) / 256, 256>>>((const float4*)W2, (uint2*)w2hp, nw4);

    k_init<<<1, 32>>>();
    k_gate<<<(NTOK * 32 + 255) / 256, 256>>>(x, Wg, bg);
    k_prefix<<<1, 1>>>();
    k_scatter<<<(NTOK + 255) / 256, 256>>>();

    dim3 grd1(HDIM / 128, 16, NEXP);   // worst-case M tiles (ne<=4096); empty tiles exit early
    k_gemm1<<<grd1, 256, SMEM_BYTES>>>(b1);
    dim3 grd2(CDIM / 128, 16, NEXP);
    k_gemm2<<<grd2, 256, SMEM_BYTES>>>(b2);
    k_combine<<<NTOK, 256>>>(out);
}

// round 8
// speedup vs baseline: 6.1789x; 1.0205x over previous
#include <cuda_runtime.h>
#include <cuda_fp16.h>
#include <math.h>
#include <stdint.h>

#define NTOK 4096
#define CDIM 1024
#define HDIM 4096
#define NEXP 8
#define NSLOT (NTOK * 2)

// GEMM geometry: block tile 256(M) x 128(N) x 64(K) fp16, 512 threads = 16 warps (4m x 4n, warp 64x32)
#define STAGE_BYTES 49152            // A 32KB + B 16KB
#define SMEM_BYTES  (3 * STAGE_BYTES)

// ---------------- static device scratch ----------------
__device__ int g_counts[NEXP];
__device__ int g_offsets[NEXP + 1];
__device__ int g_cursor[NEXP];
__device__ __align__(16) int g_rtok[NSLOT];
__device__ int g_e1[NTOK], g_e2[NTOK];
__device__ int g_s1[NTOK], g_s2[NTOK];
__device__ float g_w1[NTOK], g_w2[NTOK];
__device__ __align__(256) __half g_x16[(size_t)NTOK * CDIM];          // 8 MiB
__device__ __align__(256) __half g_w1h[(size_t)NEXP * CDIM * HDIM];   // 64 MiB
__device__ __align__(256) __half g_w2h[(size_t)NEXP * HDIM * CDIM];   // 64 MiB
__device__ __align__(256) __half g_h[(size_t)NSLOT * HDIM];           // 64 MiB
__device__ __align__(256) float  g_y[(size_t)NSLOT * CDIM];           // 32 MiB

// ---------------- helpers ----------------
__device__ __forceinline__ uint32_t smem_u32(const void* p) {
    uint32_t a;
    asm("{ .reg .u64 t; cvta.to.shared.u64 t, %1; cvt.u32.u64 %0, t; }" : "=r"(a) : "l"(p));
    return a;
}
#define SWZ(o)    ((o) ^ ((((uint32_t)(o)) >> 3) & 0x70u))   // 128B rows
#define SWZ256(o) ((o) ^ ((((uint32_t)(o)) >> 4) & 0x70u))   // 256B rows

__device__ __forceinline__ void cp16(uint32_t dst, const void* src) {
    asm volatile("cp.async.cg.shared.global [%0], [%1], 16;" :: "r"(dst), "l"(src) : "memory");
}
__device__ __forceinline__ void ldsm4(uint32_t& r0, uint32_t& r1, uint32_t& r2, uint32_t& r3, uint32_t a) {
    asm volatile("ldmatrix.sync.aligned.m8n8.x4.shared.b16 {%0,%1,%2,%3}, [%4];"
                 : "=r"(r0), "=r"(r1), "=r"(r2), "=r"(r3) : "r"(a));
}
__device__ __forceinline__ void ldsm4t(uint32_t& r0, uint32_t& r1, uint32_t& r2, uint32_t& r3, uint32_t a) {
    asm volatile("ldmatrix.sync.aligned.m8n8.x4.trans.shared.b16 {%0,%1,%2,%3}, [%4];"
                 : "=r"(r0), "=r"(r1), "=r"(r2), "=r"(r3) : "r"(a));
}
__device__ __forceinline__ void mma_f16(float* c, uint32_t a0, uint32_t a1, uint32_t a2, uint32_t a3,
                                        uint32_t b0, uint32_t b1) {
    asm volatile(
        "mma.sync.aligned.m16n8k16.row.col.f32.f16.f16.f32 "
        "{%0,%1,%2,%3}, {%4,%5,%6,%7}, {%8,%9}, {%0,%1,%2,%3};"
        : "+f"(c[0]), "+f"(c[1]), "+f"(c[2]), "+f"(c[3])
        : "r"(a0), "r"(a1), "r"(a2), "r"(a3), "r"(b0), "r"(b1));
}
__device__ __forceinline__ float gelu_exact(float v) {
    return 0.5f * v * (1.0f + erff(v * 0.70710678118654752f));
}

// ---------------- merged fp32->fp16 convert (x, W1, W2) + counts init ----------------
#define NX4 (NTOK * CDIM / 4)
#define NW4 (NEXP * CDIM * HDIM / 4)
__global__ void k_cvt_all(const float4* __restrict__ x, const float4* __restrict__ W1,
                          const float4* __restrict__ W2) {
    uint32_t i = blockIdx.x * blockDim.x + threadIdx.x;
    if (i < NEXP) g_counts[i] = 0;
    const float4* src;
    uint2* dst;
    uint32_t idx;
    if (i < NX4) {
        src = x;   dst = (uint2*)g_x16; idx = i;
    } else if (i < NX4 + NW4) {
        src = W1;  dst = (uint2*)g_w1h; idx = i - NX4;
    } else if (i < NX4 + 2 * NW4) {
        src = W2;  dst = (uint2*)g_w2h; idx = i - NX4 - NW4;
    } else return;
    float4 v = src[idx];
    __half2 lo = __floats2half2_rn(v.x, v.y);
    __half2 hi = __floats2half2_rn(v.z, v.w);
    uint2 o;
    o.x = *(uint32_t*)&lo;
    o.y = *(uint32_t*)&hi;
    dst[idx] = o;
}

// ---------------- routing kernels ----------------
__global__ void k_gate(const float* __restrict__ x, const float* __restrict__ Wg,
                       const float* __restrict__ bg) {
    int warp = (blockIdx.x * blockDim.x + threadIdx.x) >> 5;
    int lane = threadIdx.x & 31;
    if (warp >= NTOK) return;
    const float* xr = x + (size_t)warp * CDIM;
    float acc[NEXP];
#pragma unroll
    for (int e = 0; e < NEXP; e++) acc[e] = 0.f;
    for (int k = lane; k < CDIM; k += 32) {
        float xv = xr[k];
        const float* wr = Wg + k * NEXP;
#pragma unroll
        for (int e = 0; e < NEXP; e++) acc[e] = fmaf(xv, wr[e], acc[e]);
    }
#pragma unroll
    for (int off = 16; off; off >>= 1)
#pragma unroll
        for (int e = 0; e < NEXP; e++)
            acc[e] += __shfl_xor_sync(0xffffffffu, acc[e], off);
    if (lane == 0) {
#pragma unroll
        for (int e = 0; e < NEXP; e++) acc[e] += bg[e];
        int b1i = 0; float b1v = acc[0];
#pragma unroll
        for (int e = 1; e < NEXP; e++) if (acc[e] > b1v) { b1v = acc[e]; b1i = e; }
        int b2i = -1; float b2v = -3.0e38f;
#pragma unroll
        for (int e = 0; e < NEXP; e++)
            if (e != b1i && acc[e] > b2v) { b2v = acc[e]; b2i = e; }
        float p2 = expf(b2v - b1v);
        float inv = 1.f / (1.f + p2);
        g_e1[warp] = b1i; g_e2[warp] = b2i;
        g_w1[warp] = inv; g_w2[warp] = p2 * inv;
        atomicAdd(&g_counts[b1i], 1);
        atomicAdd(&g_counts[b2i], 1);
    }
}

__global__ void k_prefix() {
    if (threadIdx.x == 0 && blockIdx.x == 0) {
        int off = 0;
        for (int e = 0; e < NEXP; e++) {
            g_offsets[e] = off;
            g_cursor[e]  = off;
            off += g_counts[e];
        }
        g_offsets[NEXP] = off;
    }
}

__global__ void k_scatter() {
    int t = blockIdx.x * blockDim.x + threadIdx.x;
    if (t >= NTOK) return;
    int s1 = atomicAdd(&g_cursor[g_e1[t]], 1);
    g_rtok[s1] = t; g_s1[t] = s1;
    int s2 = atomicAdd(&g_cursor[g_e2[t]], 1);
    g_rtok[s2] = t; g_s2[t] = s2;
}

// ---------------- fp16 HMMA mainloop (256x128x64, 512 thr, 3-stage cp.async) ----------------
// Stage: A [256 m][64 k] swizzled 128B rows (32KB); B [64 k][128 n] swizzled 256B rows (16KB).
// 16 warps as 4(m) x 4(n): warp tile 64x32; ms 0..3 (m16), ns 0..3 (n8), ks 0..3 (k16).
template <int NCH>
__device__ __forceinline__ void mma_loop(
    uint32_t sb, const __half* const (&ap)[4], const __half* bsrc, int ldb,
    int tid, float (&acc)[4][4][4])
{
    const int lane = tid & 31, wid = tid >> 5;
    const int wm = (wid >> 2) * 64, wn = (wid & 3) * 32;

    uint32_t adst[4];
#pragma unroll
    for (int j = 0; j < 4; j++)
        adst[j] = SWZ((uint32_t)((tid >> 3) + 64 * j) * 128u + (uint32_t)(tid & 7) * 16u);
    uint32_t bdst[2];
#pragma unroll
    for (int j = 0; j < 2; j++)
        bdst[j] = 32768u + SWZ256((uint32_t)((tid >> 4) + 32 * j) * 256u + (uint32_t)(tid & 15) * 16u);

#define CPS(ch, s)                                                                    \
    {                                                                                 \
        uint32_t base = sb + (uint32_t)(s) * STAGE_BYTES;                             \
_Pragma("unroll")                                                                     \
        for (int j = 0; j < 4; j++)                                                   \
            cp16(base + adst[j], ap[j] + (size_t)(ch) * 64);                          \
_Pragma("unroll")                                                                     \
        for (int j = 0; j < 2; j++)                                                   \
            cp16(base + bdst[j], bsrc + ((size_t)(ch) * 64 + 32 * j) * ldb);          \
    }

    CPS(0, 0);
    asm volatile("cp.async.commit_group;" ::: "memory");
    CPS(1, 1);
    asm volatile("cp.async.commit_group;" ::: "memory");

    for (int i = 0; i < NCH; i++) {
        const bool pf = (i + 2) < NCH;
        asm volatile("cp.async.wait_group 1;" ::: "memory");
        __syncthreads();
        if (pf) CPS(i + 2, (i + 2) % 3);
        asm volatile("cp.async.commit_group;" ::: "memory");

        uint32_t As = sb + (uint32_t)(i % 3) * STAGE_BYTES;
        uint32_t Bb = As + 32768u;
#pragma unroll
        for (int ks = 0; ks < 4; ks++) {
            uint32_t bq[4][2];
#pragma unroll
            for (int p = 0; p < 2; p++) {
                int g = lane >> 3, r = lane & 7;
                uint32_t krow = (uint32_t)(ks * 16 + (g & 1) * 8 + r);
                uint32_t nby  = (uint32_t)(wn + p * 16 + (g >> 1) * 8) * 2u;
                uint32_t addr = Bb + SWZ256(krow * 256u + nby);
                ldsm4t(bq[2 * p][0], bq[2 * p][1], bq[2 * p + 1][0], bq[2 * p + 1][1], addr);
            }
#pragma unroll
            for (int ms = 0; ms < 4; ms++) {
                uint32_t row  = (uint32_t)(wm + ms * 16 + (lane & 15));
                uint32_t colb = (uint32_t)(ks * 32 + (lane >> 4) * 16);
                uint32_t addr = As + SWZ(row * 128u + colb);
                uint32_t a0, a1, a2, a3;
                ldsm4(a0, a1, a2, a3, addr);
#pragma unroll
                for (int ns = 0; ns < 4; ns++)
                    mma_f16(acc[ms][ns], a0, a1, a2, a3, bq[ns][0], bq[ns][1]);
            }
        }
    }
#undef CPS
}

// ---------------- GEMM1: h = gelu(x16_gathered @ W1h[e] + b1[e]) ----------------
__global__ __launch_bounds__(512)
void k_gemm1(const float* __restrict__ b1) {
    const int e  = blockIdx.z;
    const int off = g_offsets[e];
    const int ne  = g_offsets[e + 1] - off;
    const int m0  = blockIdx.y * 256;
    if (m0 >= ne) return;
    const int n0  = blockIdx.x * 128;

    extern __shared__ __align__(1024) char smem[];
    uint32_t sb = smem_u32(smem);
    const int tid = threadIdx.x;

    const __half* ap[4];
#pragma unroll
    for (int j = 0; j < 4; j++) {
        int r = m0 + (tid >> 3) + 64 * j;
        int tok = g_rtok[off + (r < ne ? r : 0)];
        ap[j] = g_x16 + (size_t)tok * CDIM + (tid & 7) * 8;
    }
    const __half* bsrc = g_w1h + (size_t)e * CDIM * HDIM +
                         (size_t)(tid >> 4) * HDIM + n0 + (tid & 15) * 8;

    float acc[4][4][4];
#pragma unroll
    for (int a = 0; a < 4; a++)
#pragma unroll
        for (int b = 0; b < 4; b++)
#pragma unroll
            for (int c = 0; c < 4; c++) acc[a][b][c] = 0.f;

    mma_loop<CDIM / 64>(sb, ap, bsrc, HDIM, tid, acc);

    const int lane = tid & 31, wid = tid >> 5;
    const int grp = lane >> 2, tq = lane & 3;
    const int wm = (wid >> 2) * 64, wn = (wid & 3) * 32;
    const float* brow = b1 + (size_t)e * HDIM + n0 + wn;
#pragma unroll
    for (int ms = 0; ms < 4; ms++)
#pragma unroll
        for (int h = 0; h < 2; h++) {
            int r = m0 + wm + ms * 16 + grp + h * 8;
            if (r < ne) {
                __half* hrow = g_h + (size_t)(off + r) * HDIM + n0 + wn;
#pragma unroll
                for (int ns = 0; ns < 4; ns++) {
                    int col = ns * 8 + 2 * tq;
                    __half2 o = __floats2half2_rn(
                        gelu_exact(acc[ms][ns][h * 2 + 0] + brow[col]),
                        gelu_exact(acc[ms][ns][h * 2 + 1] + brow[col + 1]));
                    *(__half2*)(hrow + col) = o;
                }
            }
        }
}

// ---------------- GEMM2: y = h_slots @ W2h[e] + b2[e] ----------------
__global__ __launch_bounds__(512)
void k_gemm2(const float* __restrict__ b2) {
    const int e  = blockIdx.z;
    const int off = g_offsets[e];
    const int ne  = g_offsets[e + 1] - off;
    const int m0  = blockIdx.y * 256;
    if (m0 >= ne) return;
    const int n0  = blockIdx.x * 128;

    extern __shared__ __align__(1024) char smem[];
    uint32_t sb = smem_u32(smem);
    const int tid = threadIdx.x;

    const __half* ap[4];
#pragma unroll
    for (int j = 0; j < 4; j++) {
        int r = m0 + (tid >> 3) + 64 * j;
        if (r >= ne) r = ne - 1;
        ap[j] = g_h + (size_t)(off + r) * HDIM + (tid & 7) * 8;
    }
    const __half* bsrc = g_w2h + (size_t)e * HDIM * CDIM +
                         (size_t)(tid >> 4) * CDIM + n0 + (tid & 15) * 8;

    float acc[4][4][4];
#pragma unroll
    for (int a = 0; a < 4; a++)
#pragma unroll
        for (int b = 0; b < 4; b++)
#pragma unroll
            for (int c = 0; c < 4; c++) acc[a][b][c] = 0.f;

    mma_loop<HDIM / 64>(sb, ap, bsrc, CDIM, tid, acc);

    const int lane = tid & 31, wid = tid >> 5;
    const int grp = lane >> 2, tq = lane & 3;
    const int wm = (wid >> 2) * 64, wn = (wid & 3) * 32;
    const float* brow = b2 + (size_t)e * CDIM + n0 + wn;
#pragma unroll
    for (int ms = 0; ms < 4; ms++)
#pragma unroll
        for (int h = 0; h < 2; h++) {
            int r = m0 + wm + ms * 16 + grp + h * 8;
            if (r < ne) {
                float* yrow = g_y + (size_t)(off + r) * CDIM + n0 + wn;
#pragma unroll
                for (int ns = 0; ns < 4; ns++) {
                    int col = ns * 8 + 2 * tq;
                    float2 o;
                    o.x = acc[ms][ns][h * 2 + 0] + brow[col];
                    o.y = acc[ms][ns][h * 2 + 1] + brow[col + 1];
                    *(float2*)(yrow + col) = o;
                }
            }
        }
}

// ---------------- combine: out[t] = w1*y[s1] + w2*y[s2] ----------------
__global__ void k_combine(float* __restrict__ out) {
    int t = blockIdx.x;
    int c = threadIdx.x * 4;
    float w1 = g_w1[t], w2 = g_w2[t];
    const float4 a = *(const float4*)(g_y + (size_t)g_s1[t] * CDIM + c);
    const float4 b = *(const float4*)(g_y + (size_t)g_s2[t] * CDIM + c);
    float4 o;
    o.x = w1 * a.x + w2 * b.x;
    o.y = w1 * a.y + w2 * b.y;
    o.z = w1 * a.z + w2 * b.z;
    o.w = w1 * a.w + w2 * b.w;
    *(float4*)(out + (size_t)t * CDIM + c) = o;
}

extern "C" void kernel_launch(void* const* d_in, const int* in_sizes, int n_in,
                              void* d_out, int out_size) {
    const float* x  = (const float*)d_in[0];
    const float* Wg = (const float*)d_in[1];
    const float* bg = (const float*)d_in[2];
    const float* W1 = (const float*)d_in[3];
    const float* b1 = (const float*)d_in[4];
    const float* W2 = (const float*)d_in[5];
    const float* b2 = (const float*)d_in[6];
    float* out = (float*)d_out;

    cudaFuncSetAttribute(k_gemm1, cudaFuncAttributeMaxDynamicSharedMemorySize, SMEM_BYTES);
    cudaFuncSetAttribute(k_gemm2, cudaFuncAttributeMaxDynamicSharedMemorySize, SMEM_BYTES);

    const int ncvt = NX4 + 2 * NW4;
    k_cvt_all<<<(ncvt + 255) / 256, 256>>>((const float4*)x, (const float4*)W1, (const float4*)W2);

    k_gate<<<(NTOK * 32 + 255) / 256, 256>>>(x, Wg, bg);
    k_prefix<<<1, 1>>>();
    k_scatter<<<(NTOK + 255) / 256, 256>>>();

    dim3 grd1(HDIM / 128, 16, NEXP);   // worst-case M tiles (ne<=4096); empty tiles exit early
    k_gemm1<<<grd1, 512, SMEM_BYTES>>>(b1);
    dim3 grd2(CDIM / 128, 16, NEXP);
    k_gemm2<<<grd2, 512, SMEM_BYTES>>>(b2);
    k_combine<<<NTOK, 256>>>(out);
}